// round 6
// baseline (speedup 1.0000x reference)
#include <cuda_runtime.h>
#include <math.h>

#define BATCH  2048
#define DIN    2048
#define DB     256
#define NHIST  63488
#define NBANK  (BATCH + NHIST)
#define NC     31

typedef unsigned long long ull;

__device__ float g_tf[BATCH * DB];
__device__ float g_qn[BATCH * DB];
__device__ float g_norm[NBANK];
__device__ float g_bns[(size_t)NBANK * DB];
__device__ float g_d[(size_t)BATCH * NBANK];   /* 512MB: fl(1-dot), class-sorted cols */
__device__ int   g_pos[NBANK];
__device__ int   g_cofs[NC + 1];
__device__ int   g_bh[256 * NC];
__device__ int   g_base[256 * NC];
__device__ int   g_ltar[BATCH];
__device__ float g_loss[BATCH];
__device__ int   g_lab64;

__device__ __forceinline__ int get_lab(const int* p, int i) {
    return g_lab64 ? p[2 * i] : p[i];
}
__device__ __forceinline__ int bank_lab(const int* cl, const int* hl, int i) {
    return (i < BATCH) ? get_lab(cl, i) : get_lab(hl, i - BATCH);
}
__device__ __forceinline__ void ffma2(ull& d, ull a, ull b) {
    asm("fma.rn.f32x2 %0, %1, %2, %0;" : "+l"(d) : "l"(a), "l"(b));
}
__device__ __forceinline__ ull dup2(float x) {
    ull r;
    asm("mov.b64 %0, {%1, %1};" : "=l"(r) : "r"(__float_as_uint(x)));
    return r;
}
__device__ __forceinline__ float2 unpack2(ull v) {
    float2 f;
    asm("mov.b64 {%0, %1}, %2;" : "=f"(f.x), "=f"(f.y) : "l"(v));
    return f;
}

__global__ void k_init(const int* __restrict__ curlab) {
    if (threadIdx.x == 0) {
        int z = 1;
        for (int i = 1; i < 32; i += 2)
            if (curlab[i] != 0) z = 0;
        g_lab64 = z;
    }
}

/* ---- stable counting sort of bank labels ---- */
__global__ void k_phist(const int* __restrict__ cl, const int* __restrict__ hl) {
    __shared__ int h[NC];
    const int tid = threadIdx.x;
    if (tid < NC) h[tid] = 0;
    __syncthreads();
    atomicAdd(&h[bank_lab(cl, hl, blockIdx.x * 256 + tid)], 1);
    __syncthreads();
    if (tid < NC) g_bh[blockIdx.x * NC + tid] = h[tid];
}

__global__ void k_pscan() {
    __shared__ int stot[NC];
    const int tid = threadIdx.x;
    if (tid < NC) {
        int t = 0;
        for (int b = 0; b < 256; ++b) t += g_bh[b * NC + tid];
        stot[tid] = t;
    }
    __syncthreads();
    if (tid == 0) {
        int run = 0;
        for (int c = 0; c < NC; ++c) { g_cofs[c] = run; run += stot[c]; }
        g_cofs[NC] = run;
    }
    __syncthreads();
    if (tid < NC) {
        int run = g_cofs[tid];
        for (int b = 0; b < 256; ++b) {
            g_base[b * NC + tid] = run;
            run += g_bh[b * NC + tid];
        }
    }
}

__global__ void k_pplace(const int* __restrict__ cl, const int* __restrict__ hl) {
    __shared__ int lab[256];
    const int tid = threadIdx.x;
    const int b0 = blockIdx.x * 256;
    lab[tid] = bank_lab(cl, hl, b0 + tid);
    __syncthreads();
    if (tid < NC) {
        int run = g_base[blockIdx.x * NC + tid];
        for (int j = 0; j < 256; ++j)
            if (lab[j] == tid) g_pos[b0 + j] = run++;
    }
}

/* ---- K1: tf = relu(target@W1+b1), sequential-k FMA chains ---- */
#define BM 64
#define BN 64
#define BK 16
__global__ void __launch_bounds__(256) k_gemm1(const float* __restrict__ A,
                                               const float* __restrict__ W,
                                               const float* __restrict__ b1) {
    __shared__ __align__(16) float As[2][BK][BM];
    __shared__ __align__(16) float Bs[2][BK][BN];
    const int tid = threadIdx.x;
    const int m0 = blockIdx.y * BM, n0 = blockIdx.x * BN;
    const int tn = tid & 31, tm = tid >> 5;
    const int ar = tid >> 2, ak = (tid & 3) << 2;
    const int br = tid >> 4, bn4 = (tid & 15) << 2;
    const int NT = DIN / BK;

    float4 aReg = *(const float4*)&A[(size_t)(m0 + ar) * DIN + ak];
    float4 bReg = *(const float4*)&W[(size_t)br * DB + n0 + bn4];
    As[0][ak + 0][ar] = aReg.x; As[0][ak + 1][ar] = aReg.y;
    As[0][ak + 2][ar] = aReg.z; As[0][ak + 3][ar] = aReg.w;
    *(float4*)&Bs[0][br][bn4] = bReg;
    __syncthreads();

    ull acc[4][2] = {};
    for (int kt = 0; kt < NT; ++kt) {
        const int cur = kt & 1;
        if (kt + 1 < NT) {
            const int kg = (kt + 1) * BK;
            aReg = *(const float4*)&A[(size_t)(m0 + ar) * DIN + kg + ak];
            bReg = *(const float4*)&W[(size_t)(kg + br) * DB + n0 + bn4];
        }
        #pragma unroll
        for (int k = 0; k < BK; ++k) {
            double2 av0 = *(const double2*)&As[cur][k][tm * 8];
            double2 av1 = *(const double2*)&As[cur][k][tm * 8 + 4];
            float2  bv  = *(const float2*)&Bs[cur][k][tn * 2];
            ull b0 = dup2(bv.x), b1d = dup2(bv.y);
            ull a0 = __double_as_longlong(av0.x), a1 = __double_as_longlong(av0.y);
            ull a2 = __double_as_longlong(av1.x), a3 = __double_as_longlong(av1.y);
            ffma2(acc[0][0], a0, b0); ffma2(acc[0][1], a0, b1d);
            ffma2(acc[1][0], a1, b0); ffma2(acc[1][1], a1, b1d);
            ffma2(acc[2][0], a2, b0); ffma2(acc[2][1], a2, b1d);
            ffma2(acc[3][0], a3, b0); ffma2(acc[3][1], a3, b1d);
        }
        if (kt + 1 < NT) {
            const int nxt = cur ^ 1;
            As[nxt][ak + 0][ar] = aReg.x; As[nxt][ak + 1][ar] = aReg.y;
            As[nxt][ak + 2][ar] = aReg.z; As[nxt][ak + 3][ar] = aReg.w;
            *(float4*)&Bs[nxt][br][bn4] = bReg;
        }
        __syncthreads();
    }
    const int n = n0 + tn * 2;
    const float bias0 = b1[n], bias1 = b1[n + 1];
    #pragma unroll
    for (int i = 0; i < 4; ++i) {
        float2 c0 = unpack2(acc[i][0]);
        float2 c1 = unpack2(acc[i][1]);
        const int m = m0 + tm * 8 + 2 * i;
        g_tf[(size_t)m * DB + n]           = fmaxf(__fadd_rn(c0.x, bias0), 0.f);
        g_tf[(size_t)m * DB + n + 1]       = fmaxf(__fadd_rn(c1.x, bias1), 0.f);
        g_tf[(size_t)(m + 1) * DB + n]     = fmaxf(__fadd_rn(c0.y, bias0), 0.f);
        g_tf[(size_t)(m + 1) * DB + n + 1] = fmaxf(__fadd_rn(c1.y, bias1), 0.f);
    }
}

/* ---- norms: sequential scalar, separate mul/add ---- */
__global__ void __launch_bounds__(256) k_norm(const float* __restrict__ hist) {
    __shared__ float tile[8][32][33];
    const int w = threadIdx.x >> 5, lane = threadIdx.x & 31;
    const int row0 = blockIdx.x * 256 + w * 32;
    const float* src = (row0 < BATCH) ? (g_tf + (size_t)row0 * DB)
                                      : (hist + (size_t)(row0 - BATCH) * DB);
    float acc = 0.f;
    for (int ch = 0; ch < 8; ++ch) {
        #pragma unroll 8
        for (int r = 0; r < 32; ++r)
            tile[w][r][lane] = src[(size_t)r * DB + ch * 32 + lane];
        __syncwarp();
        #pragma unroll 8
        for (int j = 0; j < 32; ++j) {
            float v = tile[w][lane][j];
            acc = __fadd_rn(acc, __fmul_rn(v, v));
        }
        __syncwarp();
    }
    g_norm[row0 + lane] = __fsqrt_rn(acc);
}

/* ---- normalize + class-sorted gather ---- */
__global__ void __launch_bounds__(256) k_qnrm(const float* __restrict__ hist) {
    const int gid = blockIdx.x * 256 + threadIdx.x;
    const int r = gid >> 6, q = (gid & 63) << 2;
    const float* src = (r < BATCH) ? (g_tf + (size_t)r * DB)
                                   : (hist + (size_t)(r - BATCH) * DB);
    float4 v = *(const float4*)(src + q);
    const float den = __fadd_rn(g_norm[r], 1e-12f);
    float4 o;
    o.x = __fdiv_rn(v.x, den); o.y = __fdiv_rn(v.y, den);
    o.z = __fdiv_rn(v.z, den); o.w = __fdiv_rn(v.w, den);
    *(float4*)(g_bns + (size_t)g_pos[r] * DB + q) = o;
    if (r < BATCH) *(float4*)(g_qn + (size_t)r * DB + q) = o;
}

/* ---- KD: g_d = fl(1 - qn.bns^T), 128x128x16 tiles, FFMA2 ---- */
#define DM 128
#define DN 128
#define DK 16
__global__ void __launch_bounds__(256, 2) k_dist() {
    __shared__ __align__(16) float As[2][DK][DM];
    __shared__ __align__(16) float Bs[2][DK][DN];
    const int tid = threadIdx.x;
    const int m0 = blockIdx.y * DM, n0 = blockIdx.x * DN;
    const int tn = tid & 15, tm = tid >> 4;
    const int lr = tid >> 1, lk = (tid & 1) << 3;
    const int NT = DB / DK;

    const float* Aq = g_qn + (size_t)(m0 + lr) * DB + lk;
    const float* Bq = g_bns + (size_t)(n0 + lr) * DB + lk;

    float4 a0 = *(const float4*)Aq, a1 = *(const float4*)(Aq + 4);
    float4 b0 = *(const float4*)Bq, b1 = *(const float4*)(Bq + 4);
    #pragma unroll
    for (int j = 0; j < 4; ++j) {
        As[0][lk + j][lr] = ((const float*)&a0)[j];
        As[0][lk + 4 + j][lr] = ((const float*)&a1)[j];
        Bs[0][lk + j][lr] = ((const float*)&b0)[j];
        Bs[0][lk + 4 + j][lr] = ((const float*)&b1)[j];
    }
    __syncthreads();

    ull acc[4][8] = {};
    for (int kt = 0; kt < NT; ++kt) {
        const int cur = kt & 1;
        if (kt + 1 < NT) {
            const int kg = (kt + 1) * DK;
            a0 = *(const float4*)(Aq + kg); a1 = *(const float4*)(Aq + kg + 4);
            b0 = *(const float4*)(Bq + kg); b1 = *(const float4*)(Bq + kg + 4);
        }
        #pragma unroll
        for (int k = 0; k < DK; ++k) {
            const float* ap = &As[cur][k][tm * 8];
            double2 avA = *(const double2*)ap;
            double2 avB = *(const double2*)(ap + 4);
            ull ra0 = __double_as_longlong(avA.x), ra1 = __double_as_longlong(avA.y);
            ull ra2 = __double_as_longlong(avB.x), ra3 = __double_as_longlong(avB.y);
            const float* bp = &Bs[cur][k][tn * 8];
            float4 bva = *(const float4*)bp;
            float4 bvb = *(const float4*)(bp + 4);
            ull bb0 = dup2(bva.x), bb1 = dup2(bva.y), bb2 = dup2(bva.z), bb3 = dup2(bva.w);
            ull bb4 = dup2(bvb.x), bb5 = dup2(bvb.y), bb6 = dup2(bvb.z), bb7 = dup2(bvb.w);
            ffma2(acc[0][0], ra0, bb0); ffma2(acc[0][1], ra0, bb1);
            ffma2(acc[0][2], ra0, bb2); ffma2(acc[0][3], ra0, bb3);
            ffma2(acc[0][4], ra0, bb4); ffma2(acc[0][5], ra0, bb5);
            ffma2(acc[0][6], ra0, bb6); ffma2(acc[0][7], ra0, bb7);
            ffma2(acc[1][0], ra1, bb0); ffma2(acc[1][1], ra1, bb1);
            ffma2(acc[1][2], ra1, bb2); ffma2(acc[1][3], ra1, bb3);
            ffma2(acc[1][4], ra1, bb4); ffma2(acc[1][5], ra1, bb5);
            ffma2(acc[1][6], ra1, bb6); ffma2(acc[1][7], ra1, bb7);
            ffma2(acc[2][0], ra2, bb0); ffma2(acc[2][1], ra2, bb1);
            ffma2(acc[2][2], ra2, bb2); ffma2(acc[2][3], ra2, bb3);
            ffma2(acc[2][4], ra2, bb4); ffma2(acc[2][5], ra2, bb5);
            ffma2(acc[2][6], ra2, bb6); ffma2(acc[2][7], ra2, bb7);
            ffma2(acc[3][0], ra3, bb0); ffma2(acc[3][1], ra3, bb1);
            ffma2(acc[3][2], ra3, bb2); ffma2(acc[3][3], ra3, bb3);
            ffma2(acc[3][4], ra3, bb4); ffma2(acc[3][5], ra3, bb5);
            ffma2(acc[3][6], ra3, bb6); ffma2(acc[3][7], ra3, bb7);
        }
        if (kt + 1 < NT) {
            const int nxt = cur ^ 1;
            #pragma unroll
            for (int j = 0; j < 4; ++j) {
                As[nxt][lk + j][lr] = ((const float*)&a0)[j];
                As[nxt][lk + 4 + j][lr] = ((const float*)&a1)[j];
                Bs[nxt][lk + j][lr] = ((const float*)&b0)[j];
                Bs[nxt][lk + 4 + j][lr] = ((const float*)&b1)[j];
            }
        }
        __syncthreads();
    }
    #pragma unroll
    for (int i = 0; i < 4; ++i) {
        float r0[8], r1[8];
        #pragma unroll
        for (int j = 0; j < 8; ++j) {
            float2 v = unpack2(acc[i][j]);
            r0[j] = __fadd_rn(1.0f, -v.x);
            r1[j] = __fadd_rn(1.0f, -v.y);
        }
        const size_t base = (size_t)(m0 + tm * 8 + 2 * i) * NBANK + n0 + tn * 8;
        *(float4*)&g_d[base]             = make_float4(r0[0], r0[1], r0[2], r0[3]);
        *(float4*)&g_d[base + 4]         = make_float4(r0[4], r0[5], r0[6], r0[7]);
        *(float4*)&g_d[base + NBANK]     = make_float4(r1[0], r1[1], r1[2], r1[3]);
        *(float4*)&g_d[base + NBANK + 4] = make_float4(r1[4], r1[5], r1[6], r1[7]);
    }
}

/* ---- ascending sequential class folds + argmin ---- */
__global__ void __launch_bounds__(256) k_tar(float* __restrict__ out) {
    const int w = threadIdx.x >> 5, lane = threadIdx.x & 31;
    const int b = blockIdx.x * 8 + w;
    const int lo = (lane < NC) ? g_cofs[lane] : 0;
    const int hi = (lane < NC) ? g_cofs[lane + 1] : 0;
    const float* row = g_d + (size_t)b * NBANK;
    float s = 0.f;
    int j = lo;
    for (; j + 4 <= hi; j += 4) {
        float v0 = row[j], v1 = row[j + 1], v2 = row[j + 2], v3 = row[j + 3];
        s = __fadd_rn(s, v0); s = __fadd_rn(s, v1);
        s = __fadd_rn(s, v2); s = __fadd_rn(s, v3);
    }
    for (; j < hi; ++j) s = __fadd_rn(s, row[j]);
    float dist = (lane < NC && hi > lo) ? __fdiv_rn(s, (float)(hi - lo))
                                        : __int_as_float(0x7f800000);
    int idx = lane;
    #pragma unroll
    for (int off = 16; off; off >>= 1) {
        float ov = __shfl_xor_sync(0xffffffffu, dist, off);
        int oi = __shfl_xor_sync(0xffffffffu, idx, off);
        if (ov < dist || (ov == dist && oi < idx)) { dist = ov; idx = oi; }
    }
    if (lane == 0) {
        g_ltar[b] = idx;
        out[BATCH + b] = (float)idx;
    }
}

/* ---- logits, argmax, per-row loss ---- */
__global__ void __launch_bounds__(256) k_logits(const float* __restrict__ Wc,
                                                const float* __restrict__ bc,
                                                float* __restrict__ out) {
    __shared__ float Ws[DB * 32];
    __shared__ float bcs[32];
    __shared__ float qrow[8][DB];
    const int tid = threadIdx.x;
    for (int i = tid; i < DB * 32; i += 256) {
        int d = i >> 5, c = i & 31;
        Ws[i] = (c < NC) ? Wc[d * NC + c] : 0.f;
    }
    if (tid < 32) bcs[tid] = (tid < NC) ? bc[tid] : 0.f;
    __syncthreads();
    const int w = tid >> 5, lane = tid & 31;
    const int b = blockIdx.x * 8 + w;
    *(float4*)&qrow[w][lane * 8]     = *(const float4*)(g_tf + (size_t)b * DB + lane * 8);
    *(float4*)&qrow[w][lane * 8 + 4] = *(const float4*)(g_tf + (size_t)b * DB + lane * 8 + 4);
    __syncwarp();
    float acc = 0.f;
    #pragma unroll 8
    for (int d = 0; d < DB; ++d) acc = __fmaf_rn(qrow[w][d], Ws[d * 32 + lane], acc);
    float logit = (lane < NC) ? __fadd_rn(acc, bcs[lane]) : -__int_as_float(0x7f800000);
    float v = logit;
    int idx = lane;
    #pragma unroll
    for (int off = 16; off; off >>= 1) {
        float ov = __shfl_xor_sync(0xffffffffu, v, off);
        int oi = __shfl_xor_sync(0xffffffffu, idx, off);
        if (ov > v || (ov == v && oi < idx)) { v = ov; idx = oi; }
    }
    const float m = v;
    float e = (lane < NC) ? expf(logit - m) : 0.f;
    #pragma unroll
    for (int off = 16; off; off >>= 1) e += __shfl_xor_sync(0xffffffffu, e, off);
    const int ltar = g_ltar[b];
    const float lt = __shfl_sync(0xffffffffu, logit, ltar);
    if (lane == 0) {
        out[b] = (float)idx;
        g_loss[b] = (logf(e) + m) - lt;
    }
}

__global__ void __launch_bounds__(256) k_final(float* __restrict__ out) {
    __shared__ float red[256];
    const int tid = threadIdx.x;
    float s = 0.f;
    for (int i = tid; i < BATCH; i += 256) s += g_loss[i];
    red[tid] = s;
    __syncthreads();
    for (int st = 128; st; st >>= 1) {
        if (tid < st) red[tid] += red[tid + st];
        __syncthreads();
    }
    if (tid == 0) out[2 * BATCH] = red[0] / (float)BATCH;
}

extern "C" void kernel_launch(void* const* d_in, const int* in_sizes, int n_in,
                              void* d_out, int out_size) {
    const float* target  = (const float*)d_in[0];
    const int*   curlab  = (const int*)d_in[1];
    const float* hist    = (const float*)d_in[2];
    const int*   histlab = (const int*)d_in[3];
    const float* W1      = (const float*)d_in[4];
    const float* b1      = (const float*)d_in[5];
    const float* Wc      = (const float*)d_in[6];
    const float* bc      = (const float*)d_in[7];
    float* out = (float*)d_out;

    k_init<<<1, 32>>>(curlab);
    k_phist<<<NBANK / 256, 256>>>(curlab, histlab);
    k_pscan<<<1, 32>>>();
    k_pplace<<<NBANK / 256, 256>>>(curlab, histlab);
    dim3 g1(DB / BN, BATCH / BM);
    k_gemm1<<<g1, 256>>>(target, W1, b1);
    k_norm<<<NBANK / 256, 256>>>(hist);
    k_qnrm<<<(NBANK * 64) / 256, 256>>>(hist);
    dim3 gd(NBANK / DN, BATCH / DM);
    k_dist<<<gd, 256>>>();
    k_tar<<<BATCH / 8, 256>>>(out);
    k_logits<<<BATCH / 8, 256>>>(Wc, bc, out);
    k_final<<<1, 256>>>(out);
}

// round 7
// speedup vs baseline: 1.0144x; 1.0144x over previous
#include <cuda_runtime.h>
#include <math.h>

#define BATCH  2048
#define DIN    2048
#define DB     256
#define NHIST  63488
#define NBANK  (BATCH + NHIST)
#define NC     31

typedef unsigned long long ull;

__device__ float g_tf[BATCH * DB];
__device__ float g_qn[BATCH * DB];
__device__ float g_norm[NBANK];
__device__ float g_bns[(size_t)NBANK * DB];
__device__ float g_dT[(size_t)NBANK * BATCH];  /* 512MB: fl(1-dot), TRANSPOSED [col][b] */
__device__ float g_dist[BATCH * 32];
__device__ int   g_pos[NBANK];
__device__ int   g_cofs[NC + 1];
__device__ int   g_bh[256 * NC];
__device__ int   g_base[256 * NC];
__device__ int   g_ltar[BATCH];
__device__ float g_loss[BATCH];
__device__ int   g_lab64;

__device__ __forceinline__ int get_lab(const int* p, int i) {
    return g_lab64 ? p[2 * i] : p[i];
}
__device__ __forceinline__ int bank_lab(const int* cl, const int* hl, int i) {
    return (i < BATCH) ? get_lab(cl, i) : get_lab(hl, i - BATCH);
}
__device__ __forceinline__ void ffma2(ull& d, ull a, ull b) {
    asm("fma.rn.f32x2 %0, %1, %2, %0;" : "+l"(d) : "l"(a), "l"(b));
}
__device__ __forceinline__ ull dup2(float x) {
    ull r;
    asm("mov.b64 %0, {%1, %1};" : "=l"(r) : "r"(__float_as_uint(x)));
    return r;
}
__device__ __forceinline__ float2 unpack2(ull v) {
    float2 f;
    asm("mov.b64 {%0, %1}, %2;" : "=f"(f.x), "=f"(f.y) : "l"(v));
    return f;
}

__global__ void k_init(const int* __restrict__ curlab) {
    if (threadIdx.x == 0) {
        int z = 1;
        for (int i = 1; i < 32; i += 2)
            if (curlab[i] != 0) z = 0;
        g_lab64 = z;
    }
}

/* ---- stable counting sort of bank labels ---- */
__global__ void k_phist(const int* __restrict__ cl, const int* __restrict__ hl) {
    __shared__ int h[NC];
    const int tid = threadIdx.x;
    if (tid < NC) h[tid] = 0;
    __syncthreads();
    atomicAdd(&h[bank_lab(cl, hl, blockIdx.x * 256 + tid)], 1);
    __syncthreads();
    if (tid < NC) g_bh[blockIdx.x * NC + tid] = h[tid];
}

__global__ void k_pscan() {
    __shared__ int stot[NC];
    const int tid = threadIdx.x;
    if (tid < NC) {
        int t = 0;
        for (int b = 0; b < 256; ++b) t += g_bh[b * NC + tid];
        stot[tid] = t;
    }
    __syncthreads();
    if (tid == 0) {
        int run = 0;
        for (int c = 0; c < NC; ++c) { g_cofs[c] = run; run += stot[c]; }
        g_cofs[NC] = run;
    }
    __syncthreads();
    if (tid < NC) {
        int run = g_cofs[tid];
        for (int b = 0; b < 256; ++b) {
            g_base[b * NC + tid] = run;
            run += g_bh[b * NC + tid];
        }
    }
}

__global__ void k_pplace(const int* __restrict__ cl, const int* __restrict__ hl) {
    __shared__ int lab[256];
    const int tid = threadIdx.x;
    const int b0 = blockIdx.x * 256;
    lab[tid] = bank_lab(cl, hl, b0 + tid);
    __syncthreads();
    if (tid < NC) {
        int run = g_base[blockIdx.x * NC + tid];
        for (int j = 0; j < 256; ++j)
            if (lab[j] == tid) g_pos[b0 + j] = run++;
    }
}

/* ---- K1: tf = relu(target@W1+b1), sequential-k FMA chains ---- */
#define BM 64
#define BN 64
#define BK 16
__global__ void __launch_bounds__(256) k_gemm1(const float* __restrict__ A,
                                               const float* __restrict__ W,
                                               const float* __restrict__ b1) {
    __shared__ __align__(16) float As[2][BK][BM];
    __shared__ __align__(16) float Bs[2][BK][BN];
    const int tid = threadIdx.x;
    const int m0 = blockIdx.y * BM, n0 = blockIdx.x * BN;
    const int tn = tid & 31, tm = tid >> 5;
    const int ar = tid >> 2, ak = (tid & 3) << 2;
    const int br = tid >> 4, bn4 = (tid & 15) << 2;
    const int NT = DIN / BK;

    float4 aReg = *(const float4*)&A[(size_t)(m0 + ar) * DIN + ak];
    float4 bReg = *(const float4*)&W[(size_t)br * DB + n0 + bn4];
    As[0][ak + 0][ar] = aReg.x; As[0][ak + 1][ar] = aReg.y;
    As[0][ak + 2][ar] = aReg.z; As[0][ak + 3][ar] = aReg.w;
    *(float4*)&Bs[0][br][bn4] = bReg;
    __syncthreads();

    ull acc[4][2] = {};
    for (int kt = 0; kt < NT; ++kt) {
        const int cur = kt & 1;
        if (kt + 1 < NT) {
            const int kg = (kt + 1) * BK;
            aReg = *(const float4*)&A[(size_t)(m0 + ar) * DIN + kg + ak];
            bReg = *(const float4*)&W[(size_t)(kg + br) * DB + n0 + bn4];
        }
        #pragma unroll
        for (int k = 0; k < BK; ++k) {
            double2 av0 = *(const double2*)&As[cur][k][tm * 8];
            double2 av1 = *(const double2*)&As[cur][k][tm * 8 + 4];
            float2  bv  = *(const float2*)&Bs[cur][k][tn * 2];
            ull b0 = dup2(bv.x), b1d = dup2(bv.y);
            ull a0 = __double_as_longlong(av0.x), a1 = __double_as_longlong(av0.y);
            ull a2 = __double_as_longlong(av1.x), a3 = __double_as_longlong(av1.y);
            ffma2(acc[0][0], a0, b0); ffma2(acc[0][1], a0, b1d);
            ffma2(acc[1][0], a1, b0); ffma2(acc[1][1], a1, b1d);
            ffma2(acc[2][0], a2, b0); ffma2(acc[2][1], a2, b1d);
            ffma2(acc[3][0], a3, b0); ffma2(acc[3][1], a3, b1d);
        }
        if (kt + 1 < NT) {
            const int nxt = cur ^ 1;
            As[nxt][ak + 0][ar] = aReg.x; As[nxt][ak + 1][ar] = aReg.y;
            As[nxt][ak + 2][ar] = aReg.z; As[nxt][ak + 3][ar] = aReg.w;
            *(float4*)&Bs[nxt][br][bn4] = bReg;
        }
        __syncthreads();
    }
    const int n = n0 + tn * 2;
    const float bias0 = b1[n], bias1 = b1[n + 1];
    #pragma unroll
    for (int i = 0; i < 4; ++i) {
        float2 c0 = unpack2(acc[i][0]);
        float2 c1 = unpack2(acc[i][1]);
        const int m = m0 + tm * 8 + 2 * i;
        g_tf[(size_t)m * DB + n]           = fmaxf(__fadd_rn(c0.x, bias0), 0.f);
        g_tf[(size_t)m * DB + n + 1]       = fmaxf(__fadd_rn(c1.x, bias1), 0.f);
        g_tf[(size_t)(m + 1) * DB + n]     = fmaxf(__fadd_rn(c0.y, bias0), 0.f);
        g_tf[(size_t)(m + 1) * DB + n + 1] = fmaxf(__fadd_rn(c1.y, bias1), 0.f);
    }
}

/* ---- norms: sequential scalar, separate mul/add ---- */
__global__ void __launch_bounds__(256) k_norm(const float* __restrict__ hist) {
    __shared__ float tile[8][32][33];
    const int w = threadIdx.x >> 5, lane = threadIdx.x & 31;
    const int row0 = blockIdx.x * 256 + w * 32;
    const float* src = (row0 < BATCH) ? (g_tf + (size_t)row0 * DB)
                                      : (hist + (size_t)(row0 - BATCH) * DB);
    float acc = 0.f;
    for (int ch = 0; ch < 8; ++ch) {
        #pragma unroll 8
        for (int r = 0; r < 32; ++r)
            tile[w][r][lane] = src[(size_t)r * DB + ch * 32 + lane];
        __syncwarp();
        #pragma unroll 8
        for (int j = 0; j < 32; ++j) {
            float v = tile[w][lane][j];
            acc = __fadd_rn(acc, __fmul_rn(v, v));
        }
        __syncwarp();
    }
    g_norm[row0 + lane] = __fsqrt_rn(acc);
}

/* ---- normalize + class-sorted gather ---- */
__global__ void __launch_bounds__(256) k_qnrm(const float* __restrict__ hist) {
    const int gid = blockIdx.x * 256 + threadIdx.x;
    const int r = gid >> 6, q = (gid & 63) << 2;
    const float* src = (r < BATCH) ? (g_tf + (size_t)r * DB)
                                   : (hist + (size_t)(r - BATCH) * DB);
    float4 v = *(const float4*)(src + q);
    const float den = __fadd_rn(g_norm[r], 1e-12f);
    float4 o;
    o.x = __fdiv_rn(v.x, den); o.y = __fdiv_rn(v.y, den);
    o.z = __fdiv_rn(v.z, den); o.w = __fdiv_rn(v.w, den);
    *(float4*)(g_bns + (size_t)g_pos[r] * DB + q) = o;
    if (r < BATCH) *(float4*)(g_qn + (size_t)r * DB + q) = o;
}

/* ---- KD: g_dT[col][b] = fl(1 - qn.bns^T), 128x128x16 tiles, FFMA2 ---- */
#define DM 128
#define DN 128
#define DK 16
__global__ void __launch_bounds__(256, 2) k_dist() {
    __shared__ __align__(16) float As[2][DK][DM];
    __shared__ __align__(16) float Bs[2][DK][DN];
    const int tid = threadIdx.x;
    const int m0 = blockIdx.y * DM, n0 = blockIdx.x * DN;
    const int tn = tid & 15, tm = tid >> 4;
    const int lr = tid >> 1, lk = (tid & 1) << 3;
    const int NT = DB / DK;

    const float* Aq = g_qn + (size_t)(m0 + lr) * DB + lk;
    const float* Bq = g_bns + (size_t)(n0 + lr) * DB + lk;

    float4 a0 = *(const float4*)Aq, a1 = *(const float4*)(Aq + 4);
    float4 b0 = *(const float4*)Bq, b1 = *(const float4*)(Bq + 4);
    #pragma unroll
    for (int j = 0; j < 4; ++j) {
        As[0][lk + j][lr] = ((const float*)&a0)[j];
        As[0][lk + 4 + j][lr] = ((const float*)&a1)[j];
        Bs[0][lk + j][lr] = ((const float*)&b0)[j];
        Bs[0][lk + 4 + j][lr] = ((const float*)&b1)[j];
    }
    __syncthreads();

    ull acc[4][8] = {};
    for (int kt = 0; kt < NT; ++kt) {
        const int cur = kt & 1;
        if (kt + 1 < NT) {
            const int kg = (kt + 1) * DK;
            a0 = *(const float4*)(Aq + kg); a1 = *(const float4*)(Aq + kg + 4);
            b0 = *(const float4*)(Bq + kg); b1 = *(const float4*)(Bq + kg + 4);
        }
        #pragma unroll
        for (int k = 0; k < DK; ++k) {
            const float* ap = &As[cur][k][tm * 8];
            double2 avA = *(const double2*)ap;
            double2 avB = *(const double2*)(ap + 4);
            ull ra0 = __double_as_longlong(avA.x), ra1 = __double_as_longlong(avA.y);
            ull ra2 = __double_as_longlong(avB.x), ra3 = __double_as_longlong(avB.y);
            const float* bp = &Bs[cur][k][tn * 8];
            float4 bva = *(const float4*)bp;
            float4 bvb = *(const float4*)(bp + 4);
            ull bb0 = dup2(bva.x), bb1 = dup2(bva.y), bb2 = dup2(bva.z), bb3 = dup2(bva.w);
            ull bb4 = dup2(bvb.x), bb5 = dup2(bvb.y), bb6 = dup2(bvb.z), bb7 = dup2(bvb.w);
            ffma2(acc[0][0], ra0, bb0); ffma2(acc[0][1], ra0, bb1);
            ffma2(acc[0][2], ra0, bb2); ffma2(acc[0][3], ra0, bb3);
            ffma2(acc[0][4], ra0, bb4); ffma2(acc[0][5], ra0, bb5);
            ffma2(acc[0][6], ra0, bb6); ffma2(acc[0][7], ra0, bb7);
            ffma2(acc[1][0], ra1, bb0); ffma2(acc[1][1], ra1, bb1);
            ffma2(acc[1][2], ra1, bb2); ffma2(acc[1][3], ra1, bb3);
            ffma2(acc[1][4], ra1, bb4); ffma2(acc[1][5], ra1, bb5);
            ffma2(acc[1][6], ra1, bb6); ffma2(acc[1][7], ra1, bb7);
            ffma2(acc[2][0], ra2, bb0); ffma2(acc[2][1], ra2, bb1);
            ffma2(acc[2][2], ra2, bb2); ffma2(acc[2][3], ra2, bb3);
            ffma2(acc[2][4], ra2, bb4); ffma2(acc[2][5], ra2, bb5);
            ffma2(acc[2][6], ra2, bb6); ffma2(acc[2][7], ra2, bb7);
            ffma2(acc[3][0], ra3, bb0); ffma2(acc[3][1], ra3, bb1);
            ffma2(acc[3][2], ra3, bb2); ffma2(acc[3][3], ra3, bb3);
            ffma2(acc[3][4], ra3, bb4); ffma2(acc[3][5], ra3, bb5);
            ffma2(acc[3][6], ra3, bb6); ffma2(acc[3][7], ra3, bb7);
        }
        if (kt + 1 < NT) {
            const int nxt = cur ^ 1;
            #pragma unroll
            for (int j = 0; j < 4; ++j) {
                As[nxt][lk + j][lr] = ((const float*)&a0)[j];
                As[nxt][lk + 4 + j][lr] = ((const float*)&a1)[j];
                Bs[nxt][lk + j][lr] = ((const float*)&b0)[j];
                Bs[nxt][lk + 4 + j][lr] = ((const float*)&b1)[j];
            }
        }
        __syncthreads();
    }
    /* transposed epilogue: per n, 8 contiguous m floats -> 2 full STG.128 */
    #pragma unroll
    for (int j = 0; j < 8; ++j) {
        float r[8];
        #pragma unroll
        for (int i = 0; i < 4; ++i) {
            float2 v = unpack2(acc[i][j]);
            r[2 * i]     = __fadd_rn(1.0f, -v.x);
            r[2 * i + 1] = __fadd_rn(1.0f, -v.y);
        }
        const size_t base = (size_t)(n0 + tn * 8 + j) * BATCH + m0 + tm * 8;
        *(float4*)&g_dT[base]     = make_float4(r[0], r[1], r[2], r[3]);
        *(float4*)&g_dT[base + 4] = make_float4(r[4], r[5], r[6], r[7]);
    }
}

/* ---- fold: warp = (class, 32-b group); coalesced columns, same seq order -- */
__global__ void __launch_bounds__(256) k_fold() {
    const int wg = blockIdx.x * 8 + (threadIdx.x >> 5);
    const int lane = threadIdx.x & 31;
    const int c = wg >> 6;          /* 0..30 */
    const int bg = wg & 63;         /* 0..63 */
    if (c >= NC) return;
    const int b = bg * 32 + lane;
    const int lo = g_cofs[c], hi = g_cofs[c + 1];
    float s = 0.f;
    int j = lo;
    for (; j + 4 <= hi; j += 4) {
        float v0 = g_dT[(size_t)j * BATCH + b];
        float v1 = g_dT[(size_t)(j + 1) * BATCH + b];
        float v2 = g_dT[(size_t)(j + 2) * BATCH + b];
        float v3 = g_dT[(size_t)(j + 3) * BATCH + b];
        s = __fadd_rn(s, v0); s = __fadd_rn(s, v1);
        s = __fadd_rn(s, v2); s = __fadd_rn(s, v3);
    }
    for (; j < hi; ++j) s = __fadd_rn(s, g_dT[(size_t)j * BATCH + b]);
    g_dist[b * 32 + c] = (hi > lo) ? __fdiv_rn(s, (float)(hi - lo))
                                   : __int_as_float(0x7f800000);
}

/* ---- argmin over classes ---- */
__global__ void __launch_bounds__(256) k_amin(float* __restrict__ out) {
    const int w = threadIdx.x >> 5, lane = threadIdx.x & 31;
    const int b = blockIdx.x * 8 + w;
    float dist = (lane < NC) ? g_dist[b * 32 + lane] : __int_as_float(0x7f800000);
    int idx = lane;
    #pragma unroll
    for (int off = 16; off; off >>= 1) {
        float ov = __shfl_xor_sync(0xffffffffu, dist, off);
        int oi = __shfl_xor_sync(0xffffffffu, idx, off);
        if (ov < dist || (ov == dist && oi < idx)) { dist = ov; idx = oi; }
    }
    if (lane == 0) {
        g_ltar[b] = idx;
        out[BATCH + b] = (float)idx;
    }
}

/* ---- logits, argmax, per-row loss ---- */
__global__ void __launch_bounds__(256) k_logits(const float* __restrict__ Wc,
                                                const float* __restrict__ bc,
                                                float* __restrict__ out) {
    __shared__ float Ws[DB * 32];
    __shared__ float bcs[32];
    __shared__ float qrow[8][DB];
    const int tid = threadIdx.x;
    for (int i = tid; i < DB * 32; i += 256) {
        int d = i >> 5, c = i & 31;
        Ws[i] = (c < NC) ? Wc[d * NC + c] : 0.f;
    }
    if (tid < 32) bcs[tid] = (tid < NC) ? bc[tid] : 0.f;
    __syncthreads();
    const int w = tid >> 5, lane = tid & 31;
    const int b = blockIdx.x * 8 + w;
    *(float4*)&qrow[w][lane * 8]     = *(const float4*)(g_tf + (size_t)b * DB + lane * 8);
    *(float4*)&qrow[w][lane * 8 + 4] = *(const float4*)(g_tf + (size_t)b * DB + lane * 8 + 4);
    __syncwarp();
    float acc = 0.f;
    #pragma unroll 8
    for (int d = 0; d < DB; ++d) acc = __fmaf_rn(qrow[w][d], Ws[d * 32 + lane], acc);
    float logit = (lane < NC) ? __fadd_rn(acc, bcs[lane]) : -__int_as_float(0x7f800000);
    float v = logit;
    int idx = lane;
    #pragma unroll
    for (int off = 16; off; off >>= 1) {
        float ov = __shfl_xor_sync(0xffffffffu, v, off);
        int oi = __shfl_xor_sync(0xffffffffu, idx, off);
        if (ov > v || (ov == v && oi < idx)) { v = ov; idx = oi; }
    }
    const float m = v;
    float e = (lane < NC) ? expf(logit - m) : 0.f;
    #pragma unroll
    for (int off = 16; off; off >>= 1) e += __shfl_xor_sync(0xffffffffu, e, off);
    const int ltar = g_ltar[b];
    const float lt = __shfl_sync(0xffffffffu, logit, ltar);
    if (lane == 0) {
        out[b] = (float)idx;
        g_loss[b] = (logf(e) + m) - lt;
    }
}

__global__ void __launch_bounds__(256) k_final(float* __restrict__ out) {
    __shared__ float red[256];
    const int tid = threadIdx.x;
    float s = 0.f;
    for (int i = tid; i < BATCH; i += 256) s += g_loss[i];
    red[tid] = s;
    __syncthreads();
    for (int st = 128; st; st >>= 1) {
        if (tid < st) red[tid] += red[tid + st];
        __syncthreads();
    }
    if (tid == 0) out[2 * BATCH] = red[0] / (float)BATCH;
}

extern "C" void kernel_launch(void* const* d_in, const int* in_sizes, int n_in,
                              void* d_out, int out_size) {
    const float* target  = (const float*)d_in[0];
    const int*   curlab  = (const int*)d_in[1];
    const float* hist    = (const float*)d_in[2];
    const int*   histlab = (const int*)d_in[3];
    const float* W1      = (const float*)d_in[4];
    const float* b1      = (const float*)d_in[5];
    const float* Wc      = (const float*)d_in[6];
    const float* bc      = (const float*)d_in[7];
    float* out = (float*)d_out;

    k_init<<<1, 32>>>(curlab);
    k_phist<<<NBANK / 256, 256>>>(curlab, histlab);
    k_pscan<<<1, 32>>>();
    k_pplace<<<NBANK / 256, 256>>>(curlab, histlab);
    dim3 g1(DB / BN, BATCH / BM);
    k_gemm1<<<g1, 256>>>(target, W1, b1);
    k_norm<<<NBANK / 256, 256>>>(hist);
    k_qnrm<<<(NBANK * 64) / 256, 256>>>(hist);
    dim3 gd(NBANK / DN, BATCH / DM);
    k_dist<<<gd, 256>>>();
    k_fold<<<(NC * 64 + 7) / 8, 256>>>();
    k_amin<<<BATCH / 8, 256>>>(out);
    k_logits<<<BATCH / 8, 256>>>(Wc, bc, out);
    k_final<<<1, 256>>>(out);
}